// round 5
// baseline (speedup 1.0000x reference)
#include <cuda_runtime.h>
#include <cstddef>

// DotMatrix on GB300 (sm_103a).
// out[b,i,j,t,c] = complex dot over m of A_i with SO3-conjugated A_j,
// concatenated over ell in {0..3} (M = 2*ell+1), tau = 32 per ell.
//
// Identity 1 (fold): sum_m A_i[m]*sign(m)*A_j[M-1-m]
//                  == sum_m (sign(m)*A_i[M-1-m]) * A_j[m]
// Identity 2 (symmetry): out[b,i,j,:] == out[b,j,i,:] (both components)
//   -> upper-triangular tile pairs only; mirror-store off-diagonal tiles.
//
// R5: fused ells with ONE barrier (all 4 half-tiles co-resident in 32KB smem),
// j-loop split across grid.z (544 blocks -> whole grid resident in one wave,
// ~46% occ), all store addressing in 32-bit with hoisted bases.

namespace cfg {
constexpr int kN = 256;
constexpr int kT = 32;                    // taus per ell
constexpr int JTB = 8;                    // j's per block (half tile)
constexpr int IT = 16;                    // i-tile = TY * KI
constexpr int KI = 2;
constexpr int TY = 8;
constexpr int NT = 32 * TY;               // 256 threads
constexpr int NB = 16;                    // 256/16 tile-blocks per dim
constexpr int NPAIRS = NB * (NB + 1) / 2; // 136
constexpr int SHF = 8192;                 // 512 * sum(M) floats = 32KB
}
// smem float offset of ell tile: 512 * ell^2 (8 j * 32 tau * 2M floats each)
__device__ __forceinline__ constexpr int soff(int ell) { return 512 * ell * ell; }

template <int ELL>
__device__ __forceinline__ void copyTile(const float* __restrict__ rep,
                                         float* __restrict__ sh,
                                         int b, int j0, int tid) {
  using namespace cfg;
  constexpr int M = 2 * ELL + 1;
  constexpr int CNT4 = JTB * kT * M * 2 / 4;  // 128*M float4
  const float4* src = reinterpret_cast<const float4*>(rep) +
                      (size_t)(b * kN + j0) * (16 * M);
  float4* dst = reinterpret_cast<float4*>(sh + soff(ELL));
#pragma unroll
  for (int k = tid; k < CNT4; k += NT) dst[k] = src[k];
}

template <int ELL>
__device__ __forceinline__ void doEll(const float* __restrict__ rep,
                                      const float* __restrict__ sh,
                                      int b, int i0, int j0,
                                      int tau, int ty, bool mirror,
                                      float2* __restrict__ out) {
  using namespace cfg;
  constexpr int M = 2 * ELL + 1;

  // A with flip+sign folded; KI i-rows, this thread's tau. L2-hot (2MB input).
  float ar[KI][M], ai[KI][M];
  unsigned ob[KI], om[KI];
#pragma unroll
  for (int ki = 0; ki < KI; ++ki) {
    const int i = i0 + ty + ki * TY;
    const float2* ab = reinterpret_cast<const float2*>(rep) +
                       (size_t)((b * kN + i) * kT + tau) * M;
#pragma unroll
    for (int m = 0; m < M; ++m) {
      float2 v = __ldg(&ab[M - 1 - m]);
      float s = ((m + ELL) & 1) ? -1.0f : 1.0f;
      ar[ki][m] = s * v.x;
      ai[ki][m] = s * v.y;
    }
    // 32-bit store bases (output has 2^25 float2 elements)
    ob[ki] = (unsigned)(((b * kN + i) * kN + j0) * 128 + ELL * kT + tau);
    om[ki] = (unsigned)(((b * kN + j0) * kN + i) * 128 + ELL * kT + tau);
  }

  const float2* bbase =
      reinterpret_cast<const float2*>(sh + soff(ELL)) + tau * M;
#pragma unroll
  for (int jl = 0; jl < JTB; ++jl) {
    const float2* bp = bbase + jl * (kT * M);
    float a1[KI], a2[KI], ci[KI];
#pragma unroll
    for (int ki = 0; ki < KI; ++ki) { a1[ki] = 0.f; a2[ki] = 0.f; ci[ki] = 0.f; }
#pragma unroll
    for (int m = 0; m < M; ++m) {
      float2 bv = bp[m];                  // conflict-free LDS.64
#pragma unroll
      for (int ki = 0; ki < KI; ++ki) {
        a1[ki] = fmaf(ar[ki][m], bv.x, a1[ki]);
        a2[ki] = fmaf(ai[ki][m], bv.y, a2[ki]);
        ci[ki] = fmaf(ar[ki][m], bv.y, ci[ki]);
        ci[ki] = fmaf(ai[ki][m], bv.x, ci[ki]);
      }
    }
#pragma unroll
    for (int ki = 0; ki < KI; ++ki) {
      float2 val = make_float2(a1[ki] - a2[ki], ci[ki]);
      __stcs(&out[ob[ki] + (unsigned)(jl * 128)], val);
      if (mirror)
        __stcs(&out[om[ki] + (unsigned)(jl * (kN * 128))], val);
    }
  }
}

__global__ void __launch_bounds__(cfg::NT, 4)
dotmat_kernel(const float* __restrict__ r0, const float* __restrict__ r1,
              const float* __restrict__ r2, const float* __restrict__ r3,
              float2* __restrict__ out) {
  using namespace cfg;
  __shared__ float sh[SHF];
  const int tau = threadIdx.x;
  const int ty  = threadIdx.y;
  const int tid = ty * 32 + tau;
  const int b   = blockIdx.y;

  // decode upper-triangular pair index p -> (bi, bj), bi <= bj
  const int p = blockIdx.x;
  int bi = (int)((33.0f - sqrtf(1089.0f - 8.0f * (float)p)) * 0.5f);
  while ((bi + 1) * (33 - (bi + 1)) / 2 <= p) ++bi;
  while (bi * (33 - bi) / 2 > p) --bi;
  const int bj = bi + (p - bi * (33 - bi) / 2);

  const int i0 = bi * IT;
  const int j0 = bj * IT + blockIdx.z * JTB;   // this block's j half-tile
  const bool mirror = (bi != bj);

  copyTile<0>(r0, sh, b, j0, tid);
  copyTile<1>(r1, sh, b, j0, tid);
  copyTile<2>(r2, sh, b, j0, tid);
  copyTile<3>(r3, sh, b, j0, tid);
  __syncthreads();                             // the only barrier

  doEll<0>(r0, sh, b, i0, j0, tau, ty, mirror, out);
  doEll<1>(r1, sh, b, i0, j0, tau, ty, mirror, out);
  doEll<2>(r2, sh, b, i0, j0, tau, ty, mirror, out);
  doEll<3>(r3, sh, b, i0, j0, tau, ty, mirror, out);
}

extern "C" void kernel_launch(void* const* d_in, const int* in_sizes, int n_in,
                              void* d_out, int out_size) {
  (void)in_sizes; (void)n_in; (void)out_size;
  dim3 grid(cfg::NPAIRS, 2, 2);   // (pair, batch, j-half) = 544 blocks
  dim3 block(32, cfg::TY);
  dotmat_kernel<<<grid, block>>>(
      (const float*)d_in[0], (const float*)d_in[1],
      (const float*)d_in[2], (const float*)d_in[3],
      (float2*)d_out);
}

// round 6
// speedup vs baseline: 1.1722x; 1.1722x over previous
#include <cuda_runtime.h>
#include <cstddef>
#include <cstdint>

// DotMatrix on GB300 (sm_103a).
// out[b,i,j,t,c] = complex dot over m of A_i with SO3-conjugated A_j,
// concatenated over ell in {0..3} (M = 2*ell+1), tau = 32 per ell.
//
// Identity 1 (fold): sum_m A_i[m]*sign(m)*A_j[M-1-m]
//                  == sum_m (sign(m)*A_i[M-1-m]) * A_j[m]
// Identity 2 (symmetry): out[b,i,j,:] == out[b,j,i,:] (both components)
//   -> upper-triangular tile pairs only; mirror-store off-diagonal tiles.
//
// R6 = R3 (best: 272 big blocks, JT=16, per-ell phases) with the serial
// copy->barrier->compute bubbles removed: cp.async double-buffered tile
// copies pipelined one ell ahead, integer pair decode.

namespace cfg {
constexpr int kN = 256;
constexpr int kT = 32;                    // taus per ell
constexpr int JT = 16;                    // j-tile
constexpr int IT = 16;                    // i-tile = TY * KI
constexpr int KI = 2;
constexpr int TY = 8;
constexpr int NT = 32 * TY;               // 256 threads
constexpr int NB = kN / JT;               // 16
constexpr int NPAIRS = NB * (NB + 1) / 2; // 136
// double buffer: region A holds ell 0/2 (max 20KB), region B ell 1/3 (28KB)
constexpr int OFF_A = 0;
constexpr int OFF_B = 5120;               // floats
constexpr int SHF = 5120 + 7168;          // 12288 floats = 48KB
}
__device__ __forceinline__ constexpr int bufOff(int ell) {
  return (ell & 1) ? cfg::OFF_B : cfg::OFF_A;
}

__device__ __forceinline__ void cpAsync16(uint32_t s, const float4* g) {
  asm volatile("cp.async.cg.shared.global [%0], [%1], 16;\n"
               :: "r"(s), "l"(g));
}
template <int N>
__device__ __forceinline__ void cpWait() {
  asm volatile("cp.async.wait_group %0;\n" :: "n"(N));
}
__device__ __forceinline__ void cpCommit() {
  asm volatile("cp.async.commit_group;\n");
}

template <int ELL>
__device__ __forceinline__ void copyAsync(const float* __restrict__ rep,
                                          uint32_t shAddr,
                                          int b, int j0, int tid) {
  using namespace cfg;
  constexpr int M = 2 * ELL + 1;
  constexpr int CNT4 = JT * kT * M * 2 / 4;   // 256*M float4
  const float4* src = reinterpret_cast<const float4*>(
      rep + (size_t)(b * kN + j0) * (kT * M * 2));
  uint32_t dst = shAddr + bufOff(ELL) * 4 + tid * 16;
#pragma unroll
  for (int k = 0; k < CNT4 / NT; ++k)          // exactly M iterations
    cpAsync16(dst + k * (NT * 16), src + tid + k * NT);
  cpCommit();
}

template <int ELL>
__device__ __forceinline__ void doEll(const float* __restrict__ rep,
                                      const float* __restrict__ sh,
                                      int b, int i0, int j0,
                                      int tau, int ty, bool mirror,
                                      float2* __restrict__ out) {
  using namespace cfg;
  constexpr int M = 2 * ELL + 1;

  // A with flip+sign folded; KI i-rows, this thread's tau (L2-hot input).
  float ar[KI][M], ai[KI][M];
  unsigned ob[KI], om[KI];
#pragma unroll
  for (int ki = 0; ki < KI; ++ki) {
    const int i = i0 + ty + ki * TY;
    const float2* ab = reinterpret_cast<const float2*>(rep) +
                       (size_t)((b * kN + i) * kT + tau) * M;
#pragma unroll
    for (int m = 0; m < M; ++m) {
      float2 v = __ldg(&ab[M - 1 - m]);
      float s = ((m + ELL) & 1) ? -1.0f : 1.0f;
      ar[ki][m] = s * v.x;
      ai[ki][m] = s * v.y;
    }
    ob[ki] = (unsigned)(((b * kN + i) * kN + j0) * 128 + ELL * kT + tau);
    om[ki] = (unsigned)(((b * kN + j0) * kN + i) * 128 + ELL * kT + tau);
  }

  const float2* bbase =
      reinterpret_cast<const float2*>(sh + bufOff(ELL)) + tau * M;
#pragma unroll 4
  for (int jl = 0; jl < JT; ++jl) {
    const float2* bp = bbase + jl * (kT * M);
    float a1[KI], a2[KI], ci[KI];
#pragma unroll
    for (int ki = 0; ki < KI; ++ki) { a1[ki] = 0.f; a2[ki] = 0.f; ci[ki] = 0.f; }
#pragma unroll
    for (int m = 0; m < M; ++m) {
      float2 bv = bp[m];                  // exactly-2-wavefront LDS.64
#pragma unroll
      for (int ki = 0; ki < KI; ++ki) {
        a1[ki] = fmaf(ar[ki][m], bv.x, a1[ki]);
        a2[ki] = fmaf(ai[ki][m], bv.y, a2[ki]);
        ci[ki] = fmaf(ar[ki][m], bv.y, ci[ki]);
        ci[ki] = fmaf(ai[ki][m], bv.x, ci[ki]);
      }
    }
#pragma unroll
    for (int ki = 0; ki < KI; ++ki) {
      float2 val = make_float2(a1[ki] - a2[ki], ci[ki]);
      __stcs(&out[ob[ki] + (unsigned)(jl * 128)], val);
      if (mirror)
        __stcs(&out[om[ki] + (unsigned)(jl * (kN * 128))], val);
    }
  }
}

__global__ void __launch_bounds__(cfg::NT, 4)
dotmat_kernel(const float* __restrict__ r0, const float* __restrict__ r1,
              const float* __restrict__ r2, const float* __restrict__ r3,
              float2* __restrict__ out) {
  using namespace cfg;
  __shared__ float sh[SHF];
  const uint32_t shAddr = (uint32_t)__cvta_generic_to_shared(sh);
  const int tau = threadIdx.x;
  const int ty  = threadIdx.y;
  const int tid = ty * 32 + tau;
  const int b   = blockIdx.y;

  // integer decode of upper-tri pair p -> (bi, bj), bi <= bj
  int p = blockIdx.x;
  int bi = 0;
  while (p >= NB - bi) { p -= NB - bi; ++bi; }
  const int bj = bi + p;

  const int i0 = bi * IT;
  const int j0 = bj * JT;
  const bool mirror = (bi != bj);

  // pipelined: copy(ell+1) in flight while compute(ell) runs
  copyAsync<0>(r0, shAddr, b, j0, tid);
  copyAsync<1>(r1, shAddr, b, j0, tid);
  cpWait<1>(); __syncthreads();                 // ell0 ready
  doEll<0>(r0, sh, b, i0, j0, tau, ty, mirror, out);
  __syncthreads();                              // done reading buf A
  copyAsync<2>(r2, shAddr, b, j0, tid);
  cpWait<1>(); __syncthreads();                 // ell1 ready
  doEll<1>(r1, sh, b, i0, j0, tau, ty, mirror, out);
  __syncthreads();                              // done reading buf B
  copyAsync<3>(r3, shAddr, b, j0, tid);
  cpWait<1>(); __syncthreads();                 // ell2 ready
  doEll<2>(r2, sh, b, i0, j0, tau, ty, mirror, out);
  cpWait<0>(); __syncthreads();                 // ell3 ready
  doEll<3>(r3, sh, b, i0, j0, tau, ty, mirror, out);
}

extern "C" void kernel_launch(void* const* d_in, const int* in_sizes, int n_in,
                              void* d_out, int out_size) {
  (void)in_sizes; (void)n_in; (void)out_size;
  dim3 grid(cfg::NPAIRS, 2);     // 136 tile pairs x 2 batches = 272 blocks
  dim3 block(32, cfg::TY);       // 256 threads
  dotmat_kernel<<<grid, block>>>(
      (const float*)d_in[0], (const float*)d_in[1],
      (const float*)d_in[2], (const float*)d_in[3],
      (float2*)d_out);
}